// round 16
// baseline (speedup 1.0000x reference)
#include <cuda_runtime.h>
#include <cuda_fp8.h>
#include <cstdint>

#define B_   4
#define H_   32
#define W_   32
#define C_   64
#define F_   128
#define NF   8
#define KC   (C_ * NF)       // 512 fp8 bytes per kernel position
#define NPIX (B_ * H_ * W_)  // 4096
#define NOUT (NPIX * F_)     // 524288

// Persistent accumulator: zero at module load; finish_kernel restores zero
// after every replay, so every graph replay sees the same initial state.
__device__ __align__(16) float g_Accum[NOUT];   // 2 MB

__device__ __forceinline__ int load_bits(const int* bp) {
    if (bp == nullptr) return 4;
    int b = bp[0];
    if (b < 1 || b > 30) b = (int)__int_as_float(b);
    if (b < 1 || b > 30) b = 4;
    return b;
}

// e4m3 encodings of integers 0..7 and 8..15 (all exact in e4m3)
#define E4M3_LUT0 0x4E4C4A4844403800ull
#define E4M3_LUT1 0x5756555453525150ull

__device__ __forceinline__ uint32_t int_to_e4m3(int v) {
    if (v < 8)  return (uint32_t)((E4M3_LUT0 >> (v * 8)) & 0xFF);
    if (v < 16) return (uint32_t)((E4M3_LUT1 >> ((v - 8) * 8)) & 0xFF);
    return (uint32_t)__nv_cvt_float_to_fp8((float)v, __NV_SATFINITE, __NV_E4M3);
}

__device__ uint64_t feat_pack_slow(int xi, int bits) {
    uint64_t p = 0;
#pragma unroll
    for (int m = 1; m <= 8; m++)
        p |= (uint64_t)int_to_e4m3((xi * m) >> bits) << (8 * (m - 1));
    return p;
}
__device__ uint64_t wt_pack_slow(int wi, int bits) {
    int s = (wi > 0) - (wi < 0);
    int m = (wi < 0 ? -wi : wi) & ((1 << bits) - 1);
    uint64_t p = 0;
    if (m >= 1 && m <= 8) p = (uint64_t)(s > 0 ? 0x38u : 0xB8u) << (8 * (m - 1));
    return p;
}

// ---------------------------------------------------------------------------
// Finish: out = relu(accum + bias); accum = 0 (restores replay invariant).
// ---------------------------------------------------------------------------
__global__ void finish_kernel(float4* __restrict__ out, const float4* __restrict__ bias4) {
    int i = blockIdx.x * blockDim.x + threadIdx.x;
    if (i >= NOUT / 4) return;
    float4* acc4 = (float4*)g_Accum;
    float4 a = acc4[i];
    float4 bv = bias4[i & 31];
    float4 o;
    o.x = fmaxf(a.x + bv.x, 0.f);
    o.y = fmaxf(a.y + bv.y, 0.f);
    o.z = fmaxf(a.z + bv.z, 0.f);
    o.w = fmaxf(a.w + bv.w, 0.f);
    out[i] = o;
    acc4[i] = make_float4(0.f, 0.f, 0.f, 0.f);
}

// ---------------------------------------------------------------------------
// Fully-fused FP8 GEMM: A tile expanded from x, B tile expanded from kern,
// both in-kernel; one barrier; 16 barrier-free k32 steps; atomicAdd epilogue
// into g_Accum. Block 64(M) x 128(N), 8 warps 2x4, grid (64, 9).
// ---------------------------------------------------------------------------
__device__ __forceinline__ void mma_e4m3(float c[4], const uint32_t a[4], const uint32_t b0,
                                         const uint32_t b1) {
    asm volatile(
        "mma.sync.aligned.m16n8k32.row.col.f32.e4m3.e4m3.f32 "
        "{%0,%1,%2,%3}, {%4,%5,%6,%7}, {%8,%9}, {%0,%1,%2,%3};\n"
        : "+f"(c[0]), "+f"(c[1]), "+f"(c[2]), "+f"(c[3])
        : "r"(a[0]), "r"(a[1]), "r"(a[2]), "r"(a[3]), "r"(b0), "r"(b1));
}
__device__ __forceinline__ void ldsm_x4(uint32_t r[4], uint32_t addr) {
    asm volatile("ldmatrix.sync.aligned.m8n8.x4.shared.b16 {%0,%1,%2,%3}, [%4];"
                 : "=r"(r[0]), "=r"(r[1]), "=r"(r[2]), "=r"(r[3]) : "r"(addr));
}

#define LDR    528                      // smem row stride bytes (512 data + 16 pad)
#define ABYTES (64 * LDR)               // 33792
#define BBYTES (128 * LDR)              // 67584
#define SMEMB  (ABYTES + BBYTES + 256)  // + featLUT/wtLUT

__global__ __launch_bounds__(256) void gemm_kernel(const float* __restrict__ x,
                                                   const float* __restrict__ kern,
                                                   const int* __restrict__ bitsPtr) {
    extern __shared__ uint8_t sm[];
    uint8_t* As = sm;                           // [64][LDR]
    uint8_t* Bs = sm + ABYTES;                  // [128][LDR]
    uint64_t* featLUT = (uint64_t*)(sm + ABYTES + BBYTES);        // 16
    uint64_t* wtLUT   = (uint64_t*)(sm + ABYTES + BBYTES + 128);  // 16

    const int tid = threadIdx.x;
    const int pos = blockIdx.y;
    const int di  = pos / 3, dj = pos - di * 3;
    const int p0  = blockIdx.x * 64;
    const int bits = load_bits(bitsPtr);

    // ---- LUTs ----
    if (tid < 16)       featLUT[tid]     = feat_pack_slow(tid, bits);
    else if (tid < 32)  wtLUT[tid - 16]  = wt_pack_slow((tid - 16) - 8, bits);
    __syncthreads();

    // ---- B: expand this position's 64x128 weights into smem ----
    // thread: f-group f4 = tid&31 (rows f4*4..+3), c-group c8 = tid>>5 (8 ch)
    {
        const int f4 = tid & 31;
        const int c8 = tid >> 5;
        const float* kp = kern + ((size_t)pos * C_ + c8 * 8) * F_ + f4 * 4;
#pragma unroll
        for (int cc = 0; cc < 8; cc++) {
            float4 kv = *(const float4*)(kp + (size_t)cc * F_);
            const float kf[4] = {kv.x, kv.y, kv.z, kv.w};
            const int colB = (c8 * 8 + cc) * 8;
#pragma unroll
            for (int j = 0; j < 4; j++) {
                int wi = (int)kf[j];
                uint64_t p = ((unsigned)(wi + 8) < 16u) ? wtLUT[wi + 8]
                                                        : wt_pack_slow(wi, bits);
                *(uint64_t*)(Bs + (f4 * 4 + j) * LDR + colB) = p;
            }
        }
    }

    // ---- A: 64 rows; 4 threads/row, 16 channels each; expand from x ----
    {
        const int r  = tid >> 2;
        const int c0 = (tid & 3) * 16;
        const int p  = p0 + r;
        const int bb = p >> 10, hh = (p >> 5) & 31, ww = p & 31;
        const int ih = hh + di - 1, iw = ww + dj - 1;
        uint64_t* dstRow = (uint64_t*)(As + r * LDR + c0 * 8);
        if ((unsigned)ih < 32u && (unsigned)iw < 32u) {
            const float* xp = x + (((size_t)bb * H_ + ih) * W_ + iw) * C_ + c0;
#pragma unroll
            for (int q = 0; q < 4; q++) {
                float4 xv = *(const float4*)(xp + q * 4);
                int xi0 = (int)xv.x, xi1 = (int)xv.y, xi2 = (int)xv.z, xi3 = (int)xv.w;
                dstRow[q * 4 + 0] = ((unsigned)xi0 < 16u) ? featLUT[xi0] : feat_pack_slow(xi0, bits);
                dstRow[q * 4 + 1] = ((unsigned)xi1 < 16u) ? featLUT[xi1] : feat_pack_slow(xi1, bits);
                dstRow[q * 4 + 2] = ((unsigned)xi2 < 16u) ? featLUT[xi2] : feat_pack_slow(xi2, bits);
                dstRow[q * 4 + 3] = ((unsigned)xi3 < 16u) ? featLUT[xi3] : feat_pack_slow(xi3, bits);
            }
        } else {
#pragma unroll
            for (int q = 0; q < 16; q++) dstRow[q] = 0ull;
        }
    }

    // fragment addressing
    const int wa = tid >> 5, lane = tid & 31;
    const int wm = wa & 1, wn = wa >> 1;
    const int fRow  = lane & 15;
    const int fColB = (lane >> 4) << 4;
    const uint32_t aBase = (uint32_t)__cvta_generic_to_shared(
        As + (wm * 32 + fRow) * LDR + fColB);
    const uint32_t bBase = (uint32_t)__cvta_generic_to_shared(
        Bs + (wn * 32 + fRow) * LDR + fColB);

    float acc[2][4][4];
#pragma unroll
    for (int mi = 0; mi < 2; mi++)
#pragma unroll
        for (int j = 0; j < 4; j++)
#pragma unroll
            for (int e = 0; e < 4; e++) acc[mi][j][e] = 0.0f;

    __syncthreads();                    // tiles ready

#pragma unroll
    for (int kk = 0; kk < 16; kk++) {
        const int kcB = kk * 32;
        uint32_t a[2][4], b[2][4];
#pragma unroll
        for (int mi = 0; mi < 2; mi++)
            ldsm_x4(a[mi], aBase + mi * 16 * LDR + kcB);
#pragma unroll
        for (int ni = 0; ni < 2; ni++)
            ldsm_x4(b[ni], bBase + ni * 16 * LDR + kcB);
#pragma unroll
        for (int mi = 0; mi < 2; mi++)
#pragma unroll
            for (int j = 0; j < 4; j++)
                mma_e4m3(acc[mi][j], a[mi], b[j >> 1][j & 1], b[j >> 1][(j & 1) + 2]);
    }

    // ---- split-K epilogue: exact-integer f32 atomics into g_Accum ----
    const int g = lane >> 2, t4 = lane & 3;
#pragma unroll
    for (int mi = 0; mi < 2; mi++) {
        int r0 = p0 + wm * 32 + mi * 16 + g;
#pragma unroll
        for (int j = 0; j < 4; j++) {
            int ccol = wn * 32 + j * 8 + t4 * 2;
            atomicAdd(&g_Accum[r0 * F_ + ccol],           acc[mi][j][0]);
            atomicAdd(&g_Accum[r0 * F_ + ccol + 1],       acc[mi][j][1]);
            atomicAdd(&g_Accum[(r0 + 8) * F_ + ccol],     acc[mi][j][2]);
            atomicAdd(&g_Accum[(r0 + 8) * F_ + ccol + 1], acc[mi][j][3]);
        }
    }
}

// ---------------------------------------------------------------------------
extern "C" void kernel_launch(void* const* d_in, const int* in_sizes, int n_in,
                              void* d_out, int out_size) {
    const float* x    = (const float*)d_in[0];
    const float* kern = (const float*)d_in[1];
    const float* bias = (const float*)d_in[2];
    const int*   bits = (n_in >= 4) ? (const int*)d_in[3] : nullptr;
    float* out = (float*)d_out;

    static int smemSet = 0;
    if (!smemSet) {
        cudaFuncSetAttribute(gemm_kernel, cudaFuncAttributeMaxDynamicSharedMemorySize, SMEMB);
        smemSet = 1;
    }

    dim3 gg(NPIX / 64, 9);
    gemm_kernel<<<gg, 256, SMEMB>>>(x, kern, bits);
    finish_kernel<<<(NOUT / 4 + 255) / 256, 256>>>((float4*)out, (const float4*)bias);
}

// round 17
// speedup vs baseline: 1.2129x; 1.2129x over previous
#include <cuda_runtime.h>
#include <cuda_fp8.h>
#include <cstdint>

#define B_   4
#define H_   32
#define W_   32
#define C_   64
#define F_   128
#define NF   8
#define KC   (C_ * NF)       // 512 fp8 bytes per kernel position
#define KTOT (9 * KC)        // 4608
#define HP   34
#define WP   34
#define NPIX (B_ * H_ * W_)  // 4096
#define NOUT (NPIX * F_)     // 524288

// Scratch (device globals — no allocation)
__device__ __align__(16) uint8_t g_Xf[B_ * HP * WP * KC]; // ~2.4 MB e4m3
__device__ __align__(16) uint8_t g_Wt[F_ * KTOT];         // ~0.6 MB e4m3
__device__ __align__(16) float   g_Part[9][NOUT];         // 18.9 MB per-pos partials

__device__ __forceinline__ int load_bits(const int* bp) {
    if (bp == nullptr) return 4;
    int b = bp[0];
    if (b < 1 || b > 30) b = (int)__int_as_float(b);
    if (b < 1 || b > 30) b = 4;
    return b;
}

// e4m3 encodings of integers 0..7 and 8..15 (all exact in e4m3)
#define E4M3_LUT0 0x4E4C4A4844403800ull
#define E4M3_LUT1 0x5756555453525150ull

__device__ __forceinline__ uint32_t int_to_e4m3(int v) {
    if (v < 8)  return (uint32_t)((E4M3_LUT0 >> (v * 8)) & 0xFF);
    if (v < 16) return (uint32_t)((E4M3_LUT1 >> ((v - 8) * 8)) & 0xFF);
    return (uint32_t)__nv_cvt_float_to_fp8((float)v, __NV_SATFINITE, __NV_E4M3);
}

__device__ uint64_t feat_pack_slow(int xi, int bits) {
    uint64_t p = 0;
#pragma unroll
    for (int m = 1; m <= 8; m++)
        p |= (uint64_t)int_to_e4m3((xi * m) >> bits) << (8 * (m - 1));
    return p;
}
__device__ uint64_t wt_pack_slow(int wi, int bits) {
    int s = (wi > 0) - (wi < 0);
    int m = (wi < 0 ? -wi : wi) & ((1 << bits) - 1);
    uint64_t p = 0;
    if (m >= 1 && m <= 8) p = (uint64_t)(s > 0 ? 0x38u : 0xB8u) << (8 * (m - 1));
    return p;
}

#define NC4    (C_ / 4)                    // 16
#define FEAT_T (B_ * HP * WP * NC4)        // 73984 (4 channels per thread)
#define WT_T   (9 * C_ * F_ / 4)           // 18432 (4 filters per thread)
#define PREP_T (FEAT_T + WT_T)             // 92416

// ---------------------------------------------------------------------------
// Prep (R13 verbatim, minus bias-init): feature + weight expand via smem LUT.
// ---------------------------------------------------------------------------
__global__ void prep_kernel(const float* __restrict__ x, const float* __restrict__ kern,
                            const int* __restrict__ bitsPtr) {
    __shared__ uint64_t featLUT[16];
    __shared__ uint64_t wtLUT[16];
    const int bits = load_bits(bitsPtr);
    const int t = threadIdx.x;
    if (t < 16) {
        featLUT[t] = feat_pack_slow(t, bits);
    } else if (t < 32) {
        wtLUT[t - 16] = wt_pack_slow((t - 16) - 8, bits);
    }
    __syncthreads();

    int idx = blockIdx.x * blockDim.x + t;
    if (idx >= PREP_T) return;

    if (idx < FEAT_T) {
        int c4 = idx & 15;
        int rr = idx >> 4;
        int wp = rr % WP; rr /= WP;
        int hp = rr % HP;
        int b  = rr / HP;

        uint64_t v[4] = {0ull, 0ull, 0ull, 0ull};
        if (hp >= 1 && hp <= H_ && wp >= 1 && wp <= W_) {
            const float4 xv = *(const float4*)(
                x + ((((b * H_) + (hp - 1)) * W_ + (wp - 1)) * C_ + c4 * 4));
            int xi0 = (int)xv.x, xi1 = (int)xv.y, xi2 = (int)xv.z, xi3 = (int)xv.w;
            v[0] = ((unsigned)xi0 < 16u) ? featLUT[xi0] : feat_pack_slow(xi0, bits);
            v[1] = ((unsigned)xi1 < 16u) ? featLUT[xi1] : feat_pack_slow(xi1, bits);
            v[2] = ((unsigned)xi2 < 16u) ? featLUT[xi2] : feat_pack_slow(xi2, bits);
            v[3] = ((unsigned)xi3 < 16u) ? featLUT[xi3] : feat_pack_slow(xi3, bits);
        }
        uint4* dst = (uint4*)(g_Xf + (size_t)idx * 32);
        dst[0] = *(uint4*)&v[0];
        dst[1] = *(uint4*)&v[2];
    } else {
        int i  = idx - FEAT_T;
        int f4 = i & 31;
        int rr = i >> 5;
        int c  = rr & 63;
        int pos = rr >> 6;

        const float4 kv = *(const float4*)(kern + (size_t)(pos * C_ + c) * F_ + f4 * 4);
        const float kf[4] = {kv.x, kv.y, kv.z, kv.w};
#pragma unroll
        for (int j = 0; j < 4; j++) {
            int wi = (int)kf[j];
            uint64_t p = ((unsigned)(wi + 8) < 16u) ? wtLUT[wi + 8] : wt_pack_slow(wi, bits);
            *(uint64_t*)(g_Wt + (size_t)(f4 * 4 + j) * KTOT + pos * KC + c * 8) = p;
        }
    }
}

// ---------------------------------------------------------------------------
// Finish: out = relu(sum of 9 partials + bias), float4 vectorized.
// ---------------------------------------------------------------------------
__global__ void finish_kernel(float4* __restrict__ out, const float4* __restrict__ bias4) {
    int i = blockIdx.x * blockDim.x + threadIdx.x;
    if (i >= NOUT / 4) return;
    float4 s = bias4[i & 31];
#pragma unroll
    for (int p = 0; p < 9; p++) {
        float4 v = ((const float4*)g_Part[p])[i];
        s.x += v.x; s.y += v.y; s.z += v.z; s.w += v.w;
    }
    s.x = fmaxf(s.x, 0.f); s.y = fmaxf(s.y, 0.f);
    s.z = fmaxf(s.z, 0.f); s.w = fmaxf(s.w, 0.f);
    out[i] = s;
}

// ---------------------------------------------------------------------------
// FP8 GEMM (R13 core verbatim): full K=512 in SMEM, one barrier, 16
// barrier-free k32 steps. Epilogue: smem-staged coalesced STG.128 to
// g_Part[pos] — NO atomics. Block 64(M) x 128(N), 8 warps 2x4, grid (64, 9).
// ---------------------------------------------------------------------------
__device__ __forceinline__ void mma_e4m3(float c[4], const uint32_t a[4], const uint32_t b0,
                                         const uint32_t b1) {
    asm volatile(
        "mma.sync.aligned.m16n8k32.row.col.f32.e4m3.e4m3.f32 "
        "{%0,%1,%2,%3}, {%4,%5,%6,%7}, {%8,%9}, {%0,%1,%2,%3};\n"
        : "+f"(c[0]), "+f"(c[1]), "+f"(c[2]), "+f"(c[3])
        : "r"(a[0]), "r"(a[1]), "r"(a[2]), "r"(a[3]), "r"(b0), "r"(b1));
}
__device__ __forceinline__ void ldsm_x4(uint32_t r[4], uint32_t addr) {
    asm volatile("ldmatrix.sync.aligned.m8n8.x4.shared.b16 {%0,%1,%2,%3}, [%4];"
                 : "=r"(r[0]), "=r"(r[1]), "=r"(r[2]), "=r"(r[3]) : "r"(addr));
}
__device__ __forceinline__ void cp16(uint32_t smemAddr, const void* gmem) {
    asm volatile("cp.async.cg.shared.global [%0], [%1], 16;" :: "r"(smemAddr), "l"(gmem));
}

#define LDR    528                      // smem row stride bytes (512 data + 16 pad)
#define ABYTES (64 * LDR)               // 33792
#define SMEMB  (ABYTES + 128 * LDR)     // 101376 total

__global__ __launch_bounds__(256) void gemm_kernel(float* __restrict__ dummy) {
    extern __shared__ uint8_t sm[];
    uint8_t* As = sm;                   // [64][LDR]
    uint8_t* Bs = sm + ABYTES;          // [128][LDR]

    const int tid = threadIdx.x;
    const int pos = blockIdx.y;
    const int di  = pos / 3, dj = pos - di * 3;
    const int p0  = blockIdx.x * 64;

    const int col  = tid & 31;          // 16B chunk column (0..31)
    const int rbase = tid >> 5;         // row base (0..7)

    // ---- A: 64 rows x 32 chunks; thread does rows rbase+8i, i=0..7 ----
#pragma unroll
    for (int i = 0; i < 8; i++) {
        int r = rbase + 8 * i;
        int p = p0 + r;
        int bb = p >> 10, hh = (p >> 5) & 31, ww = p & 31;
        const uint8_t* src = g_Xf + ((bb * HP + hh + di) * WP + (ww + dj)) * KC + col * 16;
        cp16((uint32_t)__cvta_generic_to_shared(As + r * LDR + col * 16), src);
    }
    // ---- B: 128 rows x 32 chunks; rows rbase+8i, i=0..15 ----
#pragma unroll
    for (int i = 0; i < 16; i++) {
        int r = rbase + 8 * i;
        const uint8_t* src = g_Wt + (size_t)r * KTOT + pos * KC + col * 16;
        cp16((uint32_t)__cvta_generic_to_shared(Bs + r * LDR + col * 16), src);
    }
    asm volatile("cp.async.commit_group;");

    // fragment addressing
    const int wa = tid >> 5, lane = tid & 31;
    const int wm = wa & 1, wn = wa >> 1;
    const int fRow  = lane & 15;
    const int fColB = (lane >> 4) << 4;
    const uint32_t aBase = (uint32_t)__cvta_generic_to_shared(
        As + (wm * 32 + fRow) * LDR + fColB);
    const uint32_t bBase = (uint32_t)__cvta_generic_to_shared(
        Bs + (wn * 32 + fRow) * LDR + fColB);

    float acc[2][4][4];
#pragma unroll
    for (int mi = 0; mi < 2; mi++)
#pragma unroll
        for (int j = 0; j < 4; j++)
#pragma unroll
            for (int e = 0; e < 4; e++) acc[mi][j][e] = 0.0f;

    asm volatile("cp.async.wait_group 0;");
    __syncthreads();                    // tiles ready

#pragma unroll
    for (int kk = 0; kk < 16; kk++) {
        const int kcB = kk * 32;
        uint32_t a[2][4], b[2][4];
#pragma unroll
        for (int mi = 0; mi < 2; mi++)
            ldsm_x4(a[mi], aBase + mi * 16 * LDR + kcB);
#pragma unroll
        for (int ni = 0; ni < 2; ni++)
            ldsm_x4(b[ni], bBase + ni * 16 * LDR + kcB);
#pragma unroll
        for (int mi = 0; mi < 2; mi++)
#pragma unroll
            for (int j = 0; j < 4; j++)
                mma_e4m3(acc[mi][j], a[mi], b[j >> 1][j & 1], b[j >> 1][(j & 1) + 2]);
    }

    // ---- epilogue: stage tile in smem (132-float stride), coalesced STG ----
    __syncthreads();                    // done reading As/Bs; reuse as stage
    float* S = (float*)sm;              // [64][132] floats = 33792 B
    const int g = lane >> 2, t4 = lane & 3;
#pragma unroll
    for (int mi = 0; mi < 2; mi++) {
        int r0 = wm * 32 + mi * 16 + g;
#pragma unroll
        for (int j = 0; j < 4; j++) {
            int ccol = wn * 32 + j * 8 + t4 * 2;
            *(float2*)&S[r0 * 132 + ccol]       = make_float2(acc[mi][j][0], acc[mi][j][1]);
            *(float2*)&S[(r0 + 8) * 132 + ccol] = make_float2(acc[mi][j][2], acc[mi][j][3]);
        }
    }
    __syncthreads();
    float4* dst = (float4*)(g_Part[pos] + (size_t)p0 * F_);
#pragma unroll
    for (int i = 0; i < 8; i++) {
        int idx = tid + i * 256;        // 2048 float4 total
        int row = idx >> 5, c4 = idx & 31;
        dst[idx] = *(const float4*)&S[row * 132 + c4 * 4];
    }
    (void)dummy;
}

// ---------------------------------------------------------------------------
extern "C" void kernel_launch(void* const* d_in, const int* in_sizes, int n_in,
                              void* d_out, int out_size) {
    const float* x    = (const float*)d_in[0];
    const float* kern = (const float*)d_in[1];
    const float* bias = (const float*)d_in[2];
    const int*   bits = (n_in >= 4) ? (const int*)d_in[3] : nullptr;
    float* out = (float*)d_out;

    static int smemSet = 0;
    if (!smemSet) {
        cudaFuncSetAttribute(gemm_kernel, cudaFuncAttributeMaxDynamicSharedMemorySize, SMEMB);
        smemSet = 1;
    }

    prep_kernel<<<(PREP_T + 255) / 256, 256>>>(x, kern, bits);
    dim3 gg(NPIX / 64, 9);
    gemm_kernel<<<gg, 256, SMEMB>>>(out);
    finish_kernel<<<(NOUT / 4 + 255) / 256, 256>>>((float4*)out, (const float4*)bias);
}